// round 9
// baseline (speedup 1.0000x reference)
#include <cuda_runtime.h>
#include <cstdint>

// ---------------- problem constants ----------------
#define BATCH    16
#define TSEQ     16384
#define CIN      8
#define GRANGES  128         // ranges per batch
#define LSTEPS   128         // TSEQ / GRANGES, multiple of CHUNK=32
#define SIGLEN   819         // 9 + 81 + 729
#define HID      256
#define SUBT     16          // subtrees per batch
#define RPS      8           // ranges per subtree
#define TSTRIDE  132         // channel-major row stride (floats): 16B-aligned, bank-spread

// ---------------- scratch (no allocations allowed) ----------------
__device__ float  g_part[BATCH * GRANGES * SIGLEN];     // fp32 range signatures
__device__ float2 g_sub [BATCH * SUBT    * SIGLEN];     // df64 subtree signatures

// ---------------- float-float (df64) helpers --------------------------
struct df2 { float hi, lo; };

__device__ __forceinline__ df2 df_add(df2 a, float b) {
    float s = __fadd_rn(a.hi, b);
    float v = __fsub_rn(s, a.hi);
    float e = __fadd_rn(__fsub_rn(a.hi, __fsub_rn(s, v)), __fsub_rn(b, v));
    e = __fadd_rn(e, a.lo);
    float hi = __fadd_rn(s, e);
    float lo = __fsub_rn(e, __fsub_rn(hi, s));
    df2 r; r.hi = hi; r.lo = lo; return r;
}

__device__ __forceinline__ df2 df_add2(df2 a, df2 b) {
    float s = __fadd_rn(a.hi, b.hi);
    float v = __fsub_rn(s, a.hi);
    float e = __fadd_rn(__fsub_rn(a.hi, __fsub_rn(s, v)), __fsub_rn(b.hi, v));
    e = __fadd_rn(e, __fadd_rn(a.lo, b.lo));
    float hi = __fadd_rn(s, e);
    float lo = __fsub_rn(e, __fsub_rn(hi, s));
    df2 r; r.hi = hi; r.lo = lo; return r;
}

__device__ __forceinline__ df2 df_fmaf(df2 a, df2 p, float q) {
    // a += p*q  (p df64, q fp32)
    float ph = __fmul_rn(p.hi, q);
    float pl = __fmaf_rn(p.hi, q, -ph);
    pl = __fmaf_rn(p.lo, q, pl);
    df2 r = df_add(a, ph);
    r.lo = __fadd_rn(r.lo, pl);
    float hi = __fadd_rn(r.hi, r.lo);
    r.lo = __fsub_rn(r.lo, __fsub_rn(hi, r.hi));
    r.hi = hi;
    return r;
}

__device__ __forceinline__ df2 df_fmaf2(df2 a, df2 p, df2 q) {
    // a += p*q  (both df64)
    float ph = __fmul_rn(p.hi, q.hi);
    float pl = __fmaf_rn(p.hi, q.hi, -ph);
    pl = __fmaf_rn(p.hi, q.lo, pl);
    pl = __fmaf_rn(p.lo, q.hi, pl);
    df2 r = df_add(a, ph);
    r.lo = __fadd_rn(r.lo, pl);
    float hi = __fadd_rn(r.hi, r.lo);
    r.lo = __fsub_rn(r.lo, __fsub_rn(hi, r.hi));
    r.hi = hi;
    return r;
}

// =====================================================================
// Kernel 1: per-range truncated signature (levels 1..3), fp32.
// (unchanged from R6 — 28.6 us measured)
// =====================================================================
__global__ __launch_bounds__(96)
void sig_partial_kernel(const float* __restrict__ x)
{
    __shared__ __align__(16) float ds [LSTEPS * 8];      // step-major (for packed k-vector)
    __shared__ __align__(16) float dst[8 * TSTRIDE];     // channel-major (for di/dj)

    const int b = blockIdx.y;
    const int g = blockIdx.x;
    const int tid = threadIdx.x;
    const float DT = 1.0f / 32.0f;

    const long base = ((long)b * TSEQ + (long)g * LSTEPS) * CIN;
    for (int idx = tid; idx < LSTEPS * 8; idx += 96) {
        int s = idx >> 3, c = idx & 7;
        float cur  = x[base + (long)s * CIN + c];
        float prev = (s & 31) ? x[base + (long)(s - 1) * CIN + c] : 0.0f;
        ds[idx] = cur - prev;
        dst[c * TSTRIDE + s] = cur - prev;
    }
    __syncthreads();

    if (tid < 81) {
        const int i = tid / 9;
        const int j = tid % 9;
        float s1i = 0.0f, s2 = 0.0f;
        uint64_t s3p[4];
        #pragma unroll
        for (int k = 0; k < 4; ++k) s3p[k] = 0ull;
        float s38 = 0.0f;
        const float4 DT4 = make_float4(DT, DT, DT, DT);

        #pragma unroll 1
        for (int s0 = 0; s0 < LSTEPS; s0 += 4) {
            float4 di4 = (i < 8) ? *reinterpret_cast<const float4*>(&dst[i * TSTRIDE + s0]) : DT4;
            float4 dj4 = (j < 8) ? *reinterpret_cast<const float4*>(&dst[j * TSTRIDE + s0]) : DT4;
            const float* dp = ds + s0 * 8;

            #pragma unroll
            for (int u = 0; u < 4; ++u, dp += 8) {
                float di = (u == 0) ? di4.x : (u == 1) ? di4.y : (u == 2) ? di4.z : di4.w;
                float dj = (u == 0) ? dj4.x : (u == 1) ? dj4.y : (u == 2) ? dj4.z : dj4.w;
                const ulonglong2* q = reinterpret_cast<const ulonglong2*>(dp);
                ulonglong2 dl = q[0];
                ulonglong2 dh = q[1];

                float a = fmaf(fmaf(di, (1.0f / 3.0f), s1i), 0.5f * dj, s2);
                uint64_t ap;
                asm("mov.b64 %0, {%1, %2};" : "=l"(ap) : "f"(a), "f"(a));
                asm("fma.rn.f32x2 %0, %1, %2, %3;" : "=l"(s3p[0]) : "l"(ap), "l"(dl.x), "l"(s3p[0]));
                asm("fma.rn.f32x2 %0, %1, %2, %3;" : "=l"(s3p[1]) : "l"(ap), "l"(dl.y), "l"(s3p[1]));
                asm("fma.rn.f32x2 %0, %1, %2, %3;" : "=l"(s3p[2]) : "l"(ap), "l"(dh.x), "l"(s3p[2]));
                asm("fma.rn.f32x2 %0, %1, %2, %3;" : "=l"(s3p[3]) : "l"(ap), "l"(dh.y), "l"(s3p[3]));
                s38 = fmaf(a, DT, s38);

                s2  = fmaf(fmaf(di, 0.5f, s1i), dj, s2);
                s1i += di;
            }
        }

        float* out = g_part + (long)(b * GRANGES + g) * SIGLEN;
        if (j == 0) out[i] = s1i;
        out[9 + tid] = s2;
        float* o3 = out + 90 + tid * 9;
        #pragma unroll
        for (int k = 0; k < 4; ++k) {
            float lo, hi;
            asm("mov.b64 {%0, %1}, %2;" : "=f"(lo), "=f"(hi) : "l"(s3p[k]));
            o3[2 * k]     = lo;
            o3[2 * k + 1] = hi;
        }
        o3[8] = s38;
    }
}

// =====================================================================
// Launch A: fold RPS range signatures -> one subtree sig, ALL state in
// registers (each thread redundantly keeps the full df64 level-1 vector
// + its own a2ij + its own c3ijk). No shared, no syncs. Prefetch 1 fold.
// Group product: c1=a1+b1 ; c2=a2+b2+a1⊗b1 ; c3=a3+b3+a1⊗b2+a2⊗b1
// (a = earlier/left operand; old a1/a2 used on the RHS.)
// Grid (SUBT, BATCH), 768 threads (729 active).
// =====================================================================
__global__ __launch_bounds__(768)
void combine8_kernel()
{
    const int b = blockIdx.y;
    const int s = blockIdx.x;
    const int t = threadIdx.x;
    if (t >= 729) return;                 // no syncs in this kernel
    const int i = t / 81;
    const int j = (t / 9) % 9;
    const int k = t % 9;

    const float* base = g_part + (long)(b * GRANGES + s * RPS) * SIGLEN;

    df2 s1[9], s2ij, c3;
    #pragma unroll
    for (int m = 0; m < 9; ++m) { s1[m].hi = base[m]; s1[m].lo = 0.f; }
    s2ij.hi = base[9 + i * 9 + j];  s2ij.lo = 0.f;
    c3.hi   = base[90 + t];         c3.lo   = 0.f;

    // prefetch fold p=1
    float nb1[9], nb2jk, nb2ij, nb3;
    {
        const float* B = base + SIGLEN;
        #pragma unroll
        for (int m = 0; m < 9; ++m) nb1[m] = B[m];
        nb2jk = B[9 + j * 9 + k];
        nb2ij = B[9 + i * 9 + j];
        nb3   = B[90 + t];
    }

    #pragma unroll 1
    for (int p = 1; p < RPS; ++p) {
        float b1v[9];
        #pragma unroll
        for (int m = 0; m < 9; ++m) b1v[m] = nb1[m];
        float b2jk = nb2jk, b2ij = nb2ij, b3 = nb3;

        if (p + 1 < RPS) {
            const float* Bn = base + (long)(p + 1) * SIGLEN;
            #pragma unroll
            for (int m = 0; m < 9; ++m) nb1[m] = Bn[m];
            nb2jk = Bn[9 + j * 9 + k];
            nb2ij = Bn[9 + i * 9 + j];
            nb3   = Bn[90 + t];
        }

        c3 = df_add(c3, b3);
        c3 = df_fmaf(c3, s1[i], b2jk);      // old a1
        c3 = df_fmaf(c3, s2ij,  b1v[k]);    // old a2
        s2ij = df_add(s2ij, b2ij);
        s2ij = df_fmaf(s2ij, s1[i], b1v[j]);  // old a1
        #pragma unroll
        for (int m = 0; m < 9; ++m) s1[m] = df_add(s1[m], b1v[m]);
    }

    float2* out = g_sub + (long)(b * SUBT + s) * SIGLEN;
    out[90 + t] = make_float2(c3.hi, c3.lo);
    if (k == 0) out[9 + i * 9 + j] = make_float2(s2ij.hi, s2ij.lo);
    if (t == 0) {
        #pragma unroll
        for (int m = 0; m < 9; ++m) out[m] = make_float2(s1[m].hi, s1[m].lo);
    }
}

// =====================================================================
// Launch B: per-batch fold of SUBT subtree sigs (df64, register state,
// syncless folds, direct loads — no prefetch, lower reg pressure),
// then log3 + MLP. Grid BATCH, 768 threads.
// =====================================================================
__global__ __launch_bounds__(768)
void final_kernel(const float* __restrict__ W1, const float* __restrict__ b1v,
                  const float* __restrict__ W2, const float* __restrict__ b2v,
                  float* __restrict__ out)
{
    __shared__ double s1sh[9];
    __shared__ double s2sh[81];
    __shared__ float  flat_sh[SIGLEN];
    __shared__ __align__(16) float hred[8][HID];
    __shared__ float osum[8];

    const int b = blockIdx.x;
    const int t = threadIdx.x;
    const bool act = t < 729;
    const int i = t / 81;
    const int j = (t / 9) % 9;
    const int k = t % 9;

    const float2* sub = g_sub + (long)(b * SUBT) * SIGLEN;

    df2 s1[9], s2ij, c3;
    if (act) {
        #pragma unroll
        for (int m = 0; m < 9; ++m) { float2 v = sub[m]; s1[m].hi = v.x; s1[m].lo = v.y; }
        { float2 v = sub[9 + i * 9 + j]; s2ij.hi = v.x; s2ij.lo = v.y; }
        { float2 v = sub[90 + t];        c3.hi   = v.x; c3.lo   = v.y; }

        #pragma unroll 1
        for (int p = 1; p < SUBT; ++p) {
            const float2* B = sub + (long)p * SIGLEN;
            df2 b1r[9];
            #pragma unroll
            for (int m = 0; m < 9; ++m) { float2 v = B[m]; b1r[m].hi = v.x; b1r[m].lo = v.y; }
            df2 b2jk, b2ij, b3;
            { float2 v = B[9 + j * 9 + k]; b2jk.hi = v.x; b2jk.lo = v.y; }
            { float2 v = B[9 + i * 9 + j]; b2ij.hi = v.x; b2ij.lo = v.y; }
            { float2 v = B[90 + t];        b3.hi   = v.x; b3.lo   = v.y; }

            c3 = df_add2(c3, b3);
            c3 = df_fmaf2(c3, s1[i], b2jk);     // old a1
            c3 = df_fmaf2(c3, s2ij,  b1r[k]);   // old a2
            s2ij = df_add2(s2ij, b2ij);
            s2ij = df_fmaf2(s2ij, s1[i], b1r[j]); // old a1
            #pragma unroll
            for (int m = 0; m < 9; ++m) s1[m] = df_add2(s1[m], b1r[m]);
        }

        // publish levels 1+2 for log3 cross-thread reads
        if (k == 0) s2sh[i * 9 + j] = (double)s2ij.hi + (double)s2ij.lo;
        if (t == 0) {
            #pragma unroll
            for (int m = 0; m < 9; ++m) s1sh[m] = (double)s1[m].hi + (double)s1[m].lo;
        }
    }
    __syncthreads();

    // ---- log3 -> flat (fp32) ----
    if (act) {
        double s1i = s1sh[i], s1j = s1sh[j], s1k = s1sh[k];
        double c3d = (double)c3.hi + (double)c3.lo;
        double l3 = c3d
                  - 0.5 * (s1i * s2sh[j * 9 + k] + s2sh[i * 9 + j] * s1k)
                  + s1i * s1j * s1k * (1.0 / 3.0);
        flat_sh[90 + t] = (float)l3;
        if (t < 81) flat_sh[9 + t] = (float)(s2sh[t] - 0.5 * s1sh[t / 9] * s1sh[t % 9]);
        if (t < 9)  flat_sh[t] = (float)s1sh[t];
    }
    __syncthreads();

    // ---- MLP layer 1: h = relu(flat @ W1 + b1) ----
    if (t < 512) {
        const int slice = t >> 6;   // 0..7
        const int jg    = t & 63;   // 0..63
        float4 acc = make_float4(0.f, 0.f, 0.f, 0.f);
        #pragma unroll 4
        for (int m = slice; m < SIGLEN; m += 8) {
            float fm = flat_sh[m];
            float4 w = *reinterpret_cast<const float4*>(W1 + (long)m * HID + jg * 4);
            acc.x = fmaf(fm, w.x, acc.x);
            acc.y = fmaf(fm, w.y, acc.y);
            acc.z = fmaf(fm, w.z, acc.z);
            acc.w = fmaf(fm, w.w, acc.w);
        }
        *reinterpret_cast<float4*>(&hred[slice][jg * 4]) = acc;
    }
    __syncthreads();

    // ---- MLP layer 2 ----
    if (t < HID) {
        float h = b1v[t];
        #pragma unroll
        for (int s = 0; s < 8; ++s) h += hred[s][t];
        h = fmaxf(h, 0.0f);
        float p = h * W2[t];
        #pragma unroll
        for (int off = 16; off > 0; off >>= 1)
            p += __shfl_down_sync(0xffffffff, p, off);
        if ((t & 31) == 0) osum[t >> 5] = p;
    }
    __syncthreads();
    if (t == 0) {
        float s = b2v[0];
        #pragma unroll
        for (int w = 0; w < 8; ++w) s += osum[w];
        out[b] = s;
    }
}

// =====================================================================
extern "C" void kernel_launch(void* const* d_in, const int* in_sizes, int n_in,
                              void* d_out, int out_size)
{
    const float* x  = (const float*)d_in[0];
    const float* W1 = (const float*)d_in[1];
    const float* b1 = (const float*)d_in[2];
    const float* W2 = (const float*)d_in[3];
    const float* b2 = (const float*)d_in[4];

    sig_partial_kernel<<<dim3(GRANGES, BATCH), 96>>>(x);
    combine8_kernel<<<dim3(SUBT, BATCH), 768>>>();
    final_kernel<<<BATCH, 768>>>(W1, b1, W2, b2, (float*)d_out);
}

// round 11
// speedup vs baseline: 1.5980x; 1.5980x over previous
#include <cuda_runtime.h>
#include <cstdint>

// ---------------- problem constants ----------------
#define BATCH    16
#define TSEQ     16384
#define CIN      8
#define GRANGES  256         // ranges per batch
#define LSTEPS   64          // TSEQ / GRANGES, multiple of CHUNK=32
#define SIGLEN   819         // 9 + 81 + 729
#define HID      256
#define SUBT     16          // subtrees per batch
#define RPS      16          // ranges per subtree (RPS*SUBT == GRANGES)
#define TSTRIDE  68          // channel-major row stride (floats): 16B-aligned, bank-spread

// ---------------- scratch (no allocations allowed) ----------------
__device__ float  g_part[BATCH * GRANGES * SIGLEN];     // fp32 range signatures
__device__ float2 g_sub [BATCH * SUBT    * SIGLEN];     // df64 subtree signatures

// ---------------- float-float (df64) helpers --------------------------
struct df2 { float hi, lo; };

__device__ __forceinline__ df2 df_add(df2 a, float b) {
    float s = __fadd_rn(a.hi, b);
    float v = __fsub_rn(s, a.hi);
    float e = __fadd_rn(__fsub_rn(a.hi, __fsub_rn(s, v)), __fsub_rn(b, v));
    e = __fadd_rn(e, a.lo);
    float hi = __fadd_rn(s, e);
    float lo = __fsub_rn(e, __fsub_rn(hi, s));
    df2 r; r.hi = hi; r.lo = lo; return r;
}

__device__ __forceinline__ df2 df_add2(df2 a, df2 b) {
    float s = __fadd_rn(a.hi, b.hi);
    float v = __fsub_rn(s, a.hi);
    float e = __fadd_rn(__fsub_rn(a.hi, __fsub_rn(s, v)), __fsub_rn(b.hi, v));
    e = __fadd_rn(e, __fadd_rn(a.lo, b.lo));
    float hi = __fadd_rn(s, e);
    float lo = __fsub_rn(e, __fsub_rn(hi, s));
    df2 r; r.hi = hi; r.lo = lo; return r;
}

__device__ __forceinline__ df2 df_fmaf(df2 a, df2 p, float q) {
    // a += p*q  (p df64, q fp32)
    float ph = __fmul_rn(p.hi, q);
    float pl = __fmaf_rn(p.hi, q, -ph);
    pl = __fmaf_rn(p.lo, q, pl);
    df2 r = df_add(a, ph);
    r.lo = __fadd_rn(r.lo, pl);
    float hi = __fadd_rn(r.hi, r.lo);
    r.lo = __fsub_rn(r.lo, __fsub_rn(hi, r.hi));
    r.hi = hi;
    return r;
}

__device__ __forceinline__ df2 df_fmaf2(df2 a, df2 p, df2 q) {
    // a += p*q  (both df64)
    float ph = __fmul_rn(p.hi, q.hi);
    float pl = __fmaf_rn(p.hi, q.hi, -ph);
    pl = __fmaf_rn(p.hi, q.lo, pl);
    pl = __fmaf_rn(p.lo, q.hi, pl);
    df2 r = df_add(a, ph);
    r.lo = __fadd_rn(r.lo, pl);
    float hi = __fadd_rn(r.hi, r.lo);
    r.lo = __fsub_rn(r.lo, __fsub_rn(hi, r.hi));
    r.hi = hi;
    return r;
}

// =====================================================================
// Kernel 1: per-range truncated signature (levels 1..3), fp32.
// Same inner loop as the measured 28.6us version; GRANGES 128->256
// (LSTEPS 64) to lift occupancy 53% -> ~80% (reg-limited, 40 regs).
// =====================================================================
__global__ __launch_bounds__(96)
void sig_partial_kernel(const float* __restrict__ x)
{
    __shared__ __align__(16) float ds [LSTEPS * 8];      // step-major (packed k-vector)
    __shared__ __align__(16) float dst[8 * TSTRIDE];     // channel-major (di/dj)

    const int b = blockIdx.y;
    const int g = blockIdx.x;
    const int tid = threadIdx.x;
    const float DT = 1.0f / 32.0f;

    const long base = ((long)b * TSEQ + (long)g * LSTEPS) * CIN;
    for (int idx = tid; idx < LSTEPS * 8; idx += 96) {
        int s = idx >> 3, c = idx & 7;
        float cur  = x[base + idx];
        float prev = (s & 31) ? x[base + idx - 8] : 0.0f;
        ds[idx] = cur - prev;
        dst[c * TSTRIDE + s] = cur - prev;
    }
    __syncthreads();

    if (tid < 81) {
        const int i = tid / 9;
        const int j = tid % 9;
        float s1i = 0.0f, s2 = 0.0f;
        uint64_t s3p[4];
        #pragma unroll
        for (int k = 0; k < 4; ++k) s3p[k] = 0ull;
        float s38 = 0.0f;
        const float4 DT4 = make_float4(DT, DT, DT, DT);

        #pragma unroll 1
        for (int s0 = 0; s0 < LSTEPS; s0 += 4) {
            float4 di4 = (i < 8) ? *reinterpret_cast<const float4*>(&dst[i * TSTRIDE + s0]) : DT4;
            float4 dj4 = (j < 8) ? *reinterpret_cast<const float4*>(&dst[j * TSTRIDE + s0]) : DT4;
            const float* dp = ds + s0 * 8;

            #pragma unroll
            for (int u = 0; u < 4; ++u, dp += 8) {
                float di = (u == 0) ? di4.x : (u == 1) ? di4.y : (u == 2) ? di4.z : di4.w;
                float dj = (u == 0) ? dj4.x : (u == 1) ? dj4.y : (u == 2) ? dj4.z : dj4.w;
                const ulonglong2* q = reinterpret_cast<const ulonglong2*>(dp);
                ulonglong2 dl = q[0];
                ulonglong2 dh = q[1];

                float a = fmaf(fmaf(di, (1.0f / 3.0f), s1i), 0.5f * dj, s2);
                uint64_t ap;
                asm("mov.b64 %0, {%1, %2};" : "=l"(ap) : "f"(a), "f"(a));
                asm("fma.rn.f32x2 %0, %1, %2, %3;" : "=l"(s3p[0]) : "l"(ap), "l"(dl.x), "l"(s3p[0]));
                asm("fma.rn.f32x2 %0, %1, %2, %3;" : "=l"(s3p[1]) : "l"(ap), "l"(dl.y), "l"(s3p[1]));
                asm("fma.rn.f32x2 %0, %1, %2, %3;" : "=l"(s3p[2]) : "l"(ap), "l"(dh.x), "l"(s3p[2]));
                asm("fma.rn.f32x2 %0, %1, %2, %3;" : "=l"(s3p[3]) : "l"(ap), "l"(dh.y), "l"(s3p[3]));
                s38 = fmaf(a, DT, s38);

                s2  = fmaf(fmaf(di, 0.5f, s1i), dj, s2);
                s1i += di;
            }
        }

        float* out = g_part + (long)(b * GRANGES + g) * SIGLEN;
        if (j == 0) out[i] = s1i;
        out[9 + tid] = s2;
        float* o3 = out + 90 + tid * 9;
        #pragma unroll
        for (int k = 0; k < 4; ++k) {
            float lo, hi;
            asm("mov.b64 {%0, %1}, %2;" : "=f"(lo), "=f"(hi) : "l"(s3p[k]));
            o3[2 * k]     = lo;
            o3[2 * k + 1] = hi;
        }
        o3[8] = s38;
    }
}

// =====================================================================
// Launch A: cooperative fold of RPS fp32 range sigs -> one df64 subtree
// sig. Level-3 accumulator in regs (thread-owned); levels 1+2 in shared
// ping-pong (hi/lo). 1 sync/fold; 3 global loads/fold/thread, prefetched.
// Index identity: for t<81 the c2-role operands B[9+t], B[t%9] equal the
// c3-role b2jk, b1k (since i==0 there) — no extra loads.
// Group product: c1=a1+b1 ; c2=a2+b2+a1⊗b1 ; c3=a3+b3+a1⊗b2+a2⊗b1.
// Grid (SUBT, BATCH), 768 threads (729 active).
// =====================================================================
__global__ __launch_bounds__(768)
void combine_kernel()
{
    __shared__ float s1h[2][9],  s1l[2][9];
    __shared__ float s2h[2][81], s2l[2][81];

    const int b = blockIdx.y;
    const int sx = blockIdx.x;
    const int t = threadIdx.x;
    const bool act = t < 729;
    const int i = t / 81;
    const int j = (t / 9) % 9;
    const int k = t % 9;

    const float* base = g_part + (long)(b * GRANGES + sx * RPS) * SIGLEN;

    df2 c3 = { 0.f, 0.f };
    float nb1k = 0.f, nb2jk = 0.f, nb3 = 0.f;
    if (act) {
        c3.hi = base[90 + t];
        if (t < 81) { s2h[0][t] = base[9 + t]; s2l[0][t] = 0.f; }
        if (t < 9)  { s1h[0][t] = base[t];     s1l[0][t] = 0.f; }
        // prefetch fold p=1
        const float* B = base + SIGLEN;
        nb1k  = B[k];
        nb2jk = B[9 + j * 9 + k];
        nb3   = B[90 + t];
    }
    __syncthreads();

    int cur = 0;
    #pragma unroll 1
    for (int p = 1; p < RPS; ++p) {
        if (act) {
            float b1k = nb1k, b2jk = nb2jk, b3 = nb3;
            if (p + 1 < RPS) {
                const float* Bn = base + (long)(p + 1) * SIGLEN;
                nb1k  = Bn[k];
                nb2jk = Bn[9 + j * 9 + k];
                nb3   = Bn[90 + t];
            }
            df2 a1i  = { s1h[cur][i],         s1l[cur][i] };
            df2 a2ij = { s2h[cur][i * 9 + j], s2l[cur][i * 9 + j] };
            c3 = df_add(c3, b3);
            c3 = df_fmaf(c3, a1i, b2jk);      // old a1
            c3 = df_fmaf(c3, a2ij, b1k);      // old a2
            if (t < 81) {   // c2 for element (t/9, t%9); operands == b2jk, b1k
                df2 a1s = { s1h[cur][t / 9], s1l[cur][t / 9] };
                df2 c2  = { s2h[cur][t],     s2l[cur][t] };
                c2 = df_add(c2, b2jk);
                c2 = df_fmaf(c2, a1s, b1k);
                s2h[cur ^ 1][t] = c2.hi;  s2l[cur ^ 1][t] = c2.lo;
            }
            if (t < 9) {    // c1: k==t so b1k==B[t]
                df2 c1 = { s1h[cur][t], s1l[cur][t] };
                c1 = df_add(c1, b1k);
                s1h[cur ^ 1][t] = c1.hi;  s1l[cur ^ 1][t] = c1.lo;
            }
        }
        __syncthreads();
        cur ^= 1;
    }

    float2* out = g_sub + (long)(b * SUBT + sx) * SIGLEN;
    if (act) {
        out[90 + t] = make_float2(c3.hi, c3.lo);
        if (t < 81) out[9 + t] = make_float2(s2h[cur][t], s2l[cur][t]);
        if (t < 9)  out[t]     = make_float2(s1h[cur][t], s1l[cur][t]);
    }
}

// =====================================================================
// Launch B: cooperative df64 fold of SUBT subtree sigs (fp32 pipes, no
// fp64 in the loop), then fp64 log3 (one shot) + MLP.
// Grid BATCH, 768 threads.
// =====================================================================
__global__ __launch_bounds__(768)
void final_kernel(const float* __restrict__ W1, const float* __restrict__ b1v,
                  const float* __restrict__ W2, const float* __restrict__ b2v,
                  float* __restrict__ out)
{
    __shared__ float s1h[2][9],  s1l[2][9];
    __shared__ float s2h[2][81], s2l[2][81];
    __shared__ float flat_sh[SIGLEN];
    __shared__ __align__(16) float hred[8][HID];
    __shared__ float osum[8];

    const int b = blockIdx.x;
    const int t = threadIdx.x;
    const bool act = t < 729;
    const int i = t / 81;
    const int j = (t / 9) % 9;
    const int k = t % 9;

    const float2* sub = g_sub + (long)(b * SUBT) * SIGLEN;

    df2 c3 = { 0.f, 0.f };
    float2 nb1k, nb2jk, nb3;
    nb1k = nb2jk = nb3 = make_float2(0.f, 0.f);
    if (act) {
        { float2 v = sub[90 + t]; c3.hi = v.x; c3.lo = v.y; }
        if (t < 81) { float2 v = sub[9 + t]; s2h[0][t] = v.x; s2l[0][t] = v.y; }
        if (t < 9)  { float2 v = sub[t];     s1h[0][t] = v.x; s1l[0][t] = v.y; }
        // prefetch fold p=1
        const float2* B = sub + SIGLEN;
        nb1k  = B[k];
        nb2jk = B[9 + j * 9 + k];
        nb3   = B[90 + t];
    }
    __syncthreads();

    int cur = 0;
    #pragma unroll 1
    for (int p = 1; p < SUBT; ++p) {
        if (act) {
            df2 b1k  = { nb1k.x,  nb1k.y  };
            df2 b2jk = { nb2jk.x, nb2jk.y };
            df2 b3   = { nb3.x,   nb3.y   };
            if (p + 1 < SUBT) {
                const float2* Bn = sub + (long)(p + 1) * SIGLEN;
                nb1k  = Bn[k];
                nb2jk = Bn[9 + j * 9 + k];
                nb3   = Bn[90 + t];
            }
            df2 a1i  = { s1h[cur][i],         s1l[cur][i] };
            df2 a2ij = { s2h[cur][i * 9 + j], s2l[cur][i * 9 + j] };
            c3 = df_add2(c3, b3);
            c3 = df_fmaf2(c3, a1i, b2jk);     // old a1
            c3 = df_fmaf2(c3, a2ij, b1k);     // old a2
            if (t < 81) {
                df2 a1s = { s1h[cur][t / 9], s1l[cur][t / 9] };
                df2 c2  = { s2h[cur][t],     s2l[cur][t] };
                c2 = df_add2(c2, b2jk);
                c2 = df_fmaf2(c2, a1s, b1k);
                s2h[cur ^ 1][t] = c2.hi;  s2l[cur ^ 1][t] = c2.lo;
            }
            if (t < 9) {
                df2 c1 = { s1h[cur][t], s1l[cur][t] };
                c1 = df_add2(c1, b1k);
                s1h[cur ^ 1][t] = c1.hi;  s1l[cur ^ 1][t] = c1.lo;
            }
        }
        __syncthreads();
        cur ^= 1;
    }

    // ---- log3 (fp64, one shot) -> flat (fp32) ----
    if (act) {
        double s1i = (double)s1h[cur][i] + (double)s1l[cur][i];
        double s1j = (double)s1h[cur][j] + (double)s1l[cur][j];
        double s1k = (double)s1h[cur][k] + (double)s1l[cur][k];
        double s2jk = (double)s2h[cur][j * 9 + k] + (double)s2l[cur][j * 9 + k];
        double s2ij = (double)s2h[cur][i * 9 + j] + (double)s2l[cur][i * 9 + j];
        double c3d  = (double)c3.hi + (double)c3.lo;
        double l3 = c3d - 0.5 * (s1i * s2jk + s2ij * s1k) + s1i * s1j * s1k * (1.0 / 3.0);
        flat_sh[90 + t] = (float)l3;
        if (t < 81) {
            double a = (double)s2h[cur][t] + (double)s2l[cur][t];
            double u = (double)s1h[cur][t / 9] + (double)s1l[cur][t / 9];
            double w = (double)s1h[cur][t % 9] + (double)s1l[cur][t % 9];
            flat_sh[9 + t] = (float)(a - 0.5 * u * w);
        }
        if (t < 9) flat_sh[t] = __fadd_rn(s1h[cur][t], s1l[cur][t]);
    }
    __syncthreads();

    // ---- MLP layer 1: h = relu(flat @ W1 + b1) ----
    if (t < 512) {
        const int slice = t >> 6;   // 0..7
        const int jg    = t & 63;   // 0..63
        float4 acc = make_float4(0.f, 0.f, 0.f, 0.f);
        #pragma unroll 4
        for (int m = slice; m < SIGLEN; m += 8) {
            float fm = flat_sh[m];
            float4 w = *reinterpret_cast<const float4*>(W1 + (long)m * HID + jg * 4);
            acc.x = fmaf(fm, w.x, acc.x);
            acc.y = fmaf(fm, w.y, acc.y);
            acc.z = fmaf(fm, w.z, acc.z);
            acc.w = fmaf(fm, w.w, acc.w);
        }
        *reinterpret_cast<float4*>(&hred[slice][jg * 4]) = acc;
    }
    __syncthreads();

    // ---- MLP layer 2 ----
    if (t < HID) {
        float h = b1v[t];
        #pragma unroll
        for (int s = 0; s < 8; ++s) h += hred[s][t];
        h = fmaxf(h, 0.0f);
        float p = h * W2[t];
        #pragma unroll
        for (int off = 16; off > 0; off >>= 1)
            p += __shfl_down_sync(0xffffffff, p, off);
        if ((t & 31) == 0) osum[t >> 5] = p;
    }
    __syncthreads();
    if (t == 0) {
        float s = b2v[0];
        #pragma unroll
        for (int w = 0; w < 8; ++w) s += osum[w];
        out[b] = s;
    }
}

// =====================================================================
extern "C" void kernel_launch(void* const* d_in, const int* in_sizes, int n_in,
                              void* d_out, int out_size)
{
    const float* x  = (const float*)d_in[0];
    const float* W1 = (const float*)d_in[1];
    const float* b1 = (const float*)d_in[2];
    const float* W2 = (const float*)d_in[3];
    const float* b2 = (const float*)d_in[4];

    sig_partial_kernel<<<dim3(GRANGES, BATCH), 96>>>(x);
    combine_kernel<<<dim3(SUBT, BATCH), 768>>>();
    final_kernel<<<BATCH, 768>>>(W1, b1, W2, b2, (float*)d_out);
}

// round 12
// speedup vs baseline: 1.6575x; 1.0372x over previous
#include <cuda_runtime.h>
#include <cstdint>

// ---------------- problem constants ----------------
#define BATCH    16
#define TSEQ     16384
#define CIN      8
#define GRANGES  256         // ranges per batch
#define LSTEPS   64          // TSEQ / GRANGES, multiple of CHUNK=32
#define SIGLEN   819         // 9 + 81 + 729
#define HID      256
#define SUBT     16          // subtrees per batch
#define RPS      16          // ranges per subtree (RPS*SUBT == GRANGES)
#define TSTRIDE  68          // channel-major row stride (floats): 16B-aligned, bank-spread

// ---------------- scratch (no allocations allowed) ----------------
__device__ float  g_part[BATCH * GRANGES * SIGLEN];     // fp32 range signatures
__device__ float2 g_sub [BATCH * SUBT    * SIGLEN];     // df64 subtree signatures

// ---------------- float-float (df64) helpers --------------------------
struct df2 { float hi, lo; };

__device__ __forceinline__ df2 df_add(df2 a, float b) {
    float s = __fadd_rn(a.hi, b);
    float v = __fsub_rn(s, a.hi);
    float e = __fadd_rn(__fsub_rn(a.hi, __fsub_rn(s, v)), __fsub_rn(b, v));
    e = __fadd_rn(e, a.lo);
    float hi = __fadd_rn(s, e);
    float lo = __fsub_rn(e, __fsub_rn(hi, s));
    df2 r; r.hi = hi; r.lo = lo; return r;
}

__device__ __forceinline__ df2 df_add2(df2 a, df2 b) {
    float s = __fadd_rn(a.hi, b.hi);
    float v = __fsub_rn(s, a.hi);
    float e = __fadd_rn(__fsub_rn(a.hi, __fsub_rn(s, v)), __fsub_rn(b.hi, v));
    e = __fadd_rn(e, __fadd_rn(a.lo, b.lo));
    float hi = __fadd_rn(s, e);
    float lo = __fsub_rn(e, __fsub_rn(hi, s));
    df2 r; r.hi = hi; r.lo = lo; return r;
}

__device__ __forceinline__ df2 df_fmaf(df2 a, df2 p, float q) {
    // a += p*q  (p df64, q fp32)
    float ph = __fmul_rn(p.hi, q);
    float pl = __fmaf_rn(p.hi, q, -ph);
    pl = __fmaf_rn(p.lo, q, pl);
    df2 r = df_add(a, ph);
    r.lo = __fadd_rn(r.lo, pl);
    float hi = __fadd_rn(r.hi, r.lo);
    r.lo = __fsub_rn(r.lo, __fsub_rn(hi, r.hi));
    r.hi = hi;
    return r;
}

__device__ __forceinline__ df2 df_fmaf2(df2 a, df2 p, df2 q) {
    // a += p*q  (both df64)
    float ph = __fmul_rn(p.hi, q.hi);
    float pl = __fmaf_rn(p.hi, q.hi, -ph);
    pl = __fmaf_rn(p.hi, q.lo, pl);
    pl = __fmaf_rn(p.lo, q.hi, pl);
    df2 r = df_add(a, ph);
    r.lo = __fadd_rn(r.lo, pl);
    float hi = __fadd_rn(r.hi, r.lo);
    r.lo = __fsub_rn(r.lo, __fsub_rn(hi, r.hi));
    r.hi = hi;
    return r;
}

// =====================================================================
// Kernel 1: per-range truncated signature (levels 1..3), fp32.
// (identical to R11 — 27.1 us measured)
// =====================================================================
__global__ __launch_bounds__(96)
void sig_partial_kernel(const float* __restrict__ x)
{
    __shared__ __align__(16) float ds [LSTEPS * 8];      // step-major (packed k-vector)
    __shared__ __align__(16) float dst[8 * TSTRIDE];     // channel-major (di/dj)

    const int b = blockIdx.y;
    const int g = blockIdx.x;
    const int tid = threadIdx.x;
    const float DT = 1.0f / 32.0f;

    const long base = ((long)b * TSEQ + (long)g * LSTEPS) * CIN;
    for (int idx = tid; idx < LSTEPS * 8; idx += 96) {
        int s = idx >> 3, c = idx & 7;
        float cur  = x[base + idx];
        float prev = (s & 31) ? x[base + idx - 8] : 0.0f;
        ds[idx] = cur - prev;
        dst[c * TSTRIDE + s] = cur - prev;
    }
    __syncthreads();

    if (tid < 81) {
        const int i = tid / 9;
        const int j = tid % 9;
        float s1i = 0.0f, s2 = 0.0f;
        uint64_t s3p[4];
        #pragma unroll
        for (int k = 0; k < 4; ++k) s3p[k] = 0ull;
        float s38 = 0.0f;
        const float4 DT4 = make_float4(DT, DT, DT, DT);

        #pragma unroll 1
        for (int s0 = 0; s0 < LSTEPS; s0 += 4) {
            float4 di4 = (i < 8) ? *reinterpret_cast<const float4*>(&dst[i * TSTRIDE + s0]) : DT4;
            float4 dj4 = (j < 8) ? *reinterpret_cast<const float4*>(&dst[j * TSTRIDE + s0]) : DT4;
            const float* dp = ds + s0 * 8;

            #pragma unroll
            for (int u = 0; u < 4; ++u, dp += 8) {
                float di = (u == 0) ? di4.x : (u == 1) ? di4.y : (u == 2) ? di4.z : di4.w;
                float dj = (u == 0) ? dj4.x : (u == 1) ? dj4.y : (u == 2) ? dj4.z : dj4.w;
                const ulonglong2* q = reinterpret_cast<const ulonglong2*>(dp);
                ulonglong2 dl = q[0];
                ulonglong2 dh = q[1];

                float a = fmaf(fmaf(di, (1.0f / 3.0f), s1i), 0.5f * dj, s2);
                uint64_t ap;
                asm("mov.b64 %0, {%1, %2};" : "=l"(ap) : "f"(a), "f"(a));
                asm("fma.rn.f32x2 %0, %1, %2, %3;" : "=l"(s3p[0]) : "l"(ap), "l"(dl.x), "l"(s3p[0]));
                asm("fma.rn.f32x2 %0, %1, %2, %3;" : "=l"(s3p[1]) : "l"(ap), "l"(dl.y), "l"(s3p[1]));
                asm("fma.rn.f32x2 %0, %1, %2, %3;" : "=l"(s3p[2]) : "l"(ap), "l"(dh.x), "l"(s3p[2]));
                asm("fma.rn.f32x2 %0, %1, %2, %3;" : "=l"(s3p[3]) : "l"(ap), "l"(dh.y), "l"(s3p[3]));
                s38 = fmaf(a, DT, s38);

                s2  = fmaf(fmaf(di, 0.5f, s1i), dj, s2);
                s1i += di;
            }
        }

        float* out = g_part + (long)(b * GRANGES + g) * SIGLEN;
        if (j == 0) out[i] = s1i;
        out[9 + tid] = s2;
        float* o3 = out + 90 + tid * 9;
        #pragma unroll
        for (int k = 0; k < 4; ++k) {
            float lo, hi;
            asm("mov.b64 {%0, %1}, %2;" : "=f"(lo), "=f"(hi) : "l"(s3p[k]));
            o3[2 * k]     = lo;
            o3[2 * k + 1] = hi;
        }
        o3[8] = s38;
    }
}

// =====================================================================
// Launch A: fold RPS fp32 range sigs -> one df64 subtree sig.
// ALL fold operands (3 floats/fold/thread) loaded to registers UPFRONT
// (45 regs, MLP~45), then RPS-1 folds of pure shared/FFMA work.
// Level-3 acc in regs; levels 1+2 in shared ping-pong. 1 sync/fold.
// Group product: c1=a1+b1 ; c2=a2+b2+a1(x)b1 ; c3=a3+b3+a1(x)b2+a2(x)b1.
// Grid (SUBT, BATCH), 768 threads (729 active).
// =====================================================================
__global__ __launch_bounds__(768)
void combine_kernel()
{
    __shared__ float s1h[2][9],  s1l[2][9];
    __shared__ float s2h[2][81], s2l[2][81];

    const int b = blockIdx.y;
    const int sx = blockIdx.x;
    const int t = threadIdx.x;
    const bool act = t < 729;
    const int i = t / 81;
    const int j = (t / 9) % 9;
    const int k = t % 9;

    const float* base = g_part + (long)(b * GRANGES + sx * RPS) * SIGLEN;

    df2 c3 = { 0.f, 0.f };
    float ob1[RPS - 1], ob2[RPS - 1], ob3[RPS - 1];
    if (act) {
        c3.hi = base[90 + t];
        if (t < 81) { s2h[0][t] = base[9 + t]; s2l[0][t] = 0.f; }
        if (t < 9)  { s1h[0][t] = base[t];     s1l[0][t] = 0.f; }
        // load ALL fold operands upfront (independent loads, deep MLP)
        #pragma unroll
        for (int p = 1; p < RPS; ++p) {
            const float* B = base + (long)p * SIGLEN;
            ob1[p - 1] = B[k];
            ob2[p - 1] = B[9 + j * 9 + k];
            ob3[p - 1] = B[90 + t];
        }
    }
    __syncthreads();

    int cur = 0;
    #pragma unroll
    for (int p = 1; p < RPS; ++p) {
        if (act) {
            float b1k = ob1[p - 1], b2jk = ob2[p - 1], b3 = ob3[p - 1];
            df2 a1i  = { s1h[cur][i],         s1l[cur][i] };
            df2 a2ij = { s2h[cur][i * 9 + j], s2l[cur][i * 9 + j] };
            c3 = df_add(c3, b3);
            c3 = df_fmaf(c3, a1i, b2jk);      // old a1
            c3 = df_fmaf(c3, a2ij, b1k);      // old a2
            if (t < 81) {   // c2 for element (t/9, t%9); operands == b2jk, b1k
                df2 a1s = { s1h[cur][t / 9], s1l[cur][t / 9] };
                df2 c2  = { s2h[cur][t],     s2l[cur][t] };
                c2 = df_add(c2, b2jk);
                c2 = df_fmaf(c2, a1s, b1k);
                s2h[cur ^ 1][t] = c2.hi;  s2l[cur ^ 1][t] = c2.lo;
            }
            if (t < 9) {    // c1: k==t so b1k==B[t]
                df2 c1 = { s1h[cur][t], s1l[cur][t] };
                c1 = df_add(c1, b1k);
                s1h[cur ^ 1][t] = c1.hi;  s1l[cur ^ 1][t] = c1.lo;
            }
        }
        __syncthreads();
        cur ^= 1;
    }

    float2* out = g_sub + (long)(b * SUBT + sx) * SIGLEN;
    if (act) {
        out[90 + t] = make_float2(c3.hi, c3.lo);
        if (t < 81) out[9 + t] = make_float2(s2h[cur][t], s2l[cur][t]);
        if (t < 9)  out[t]     = make_float2(s1h[cur][t], s1l[cur][t]);
    }
}

// =====================================================================
// Launch B: fold SUBT df64 subtree sigs (df64 on fp32 pipes), operands
// register-batched in two halves (folds 1..8, then 9..15), then fp64
// log3 (one shot) + MLP. Grid BATCH, 768 threads.
// =====================================================================
#define NB1 8                       // folds 1..8 in batch 1
#define NB2 (SUBT - 1 - NB1)        // folds 9..15 in batch 2 (7)

__global__ __launch_bounds__(768)
void final_kernel(const float* __restrict__ W1, const float* __restrict__ b1v,
                  const float* __restrict__ W2, const float* __restrict__ b2v,
                  float* __restrict__ out)
{
    __shared__ float s1h[2][9],  s1l[2][9];
    __shared__ float s2h[2][81], s2l[2][81];
    __shared__ float flat_sh[SIGLEN];
    __shared__ __align__(16) float hred[8][HID];
    __shared__ float osum[8];

    const int b = blockIdx.x;
    const int t = threadIdx.x;
    const bool act = t < 729;
    const int i = t / 81;
    const int j = (t / 9) % 9;
    const int k = t % 9;

    const float2* sub = g_sub + (long)(b * SUBT) * SIGLEN;

    df2 c3 = { 0.f, 0.f };
    float2 ob1[NB1], ob2[NB1], ob3[NB1];
    if (act) {
        { float2 v = sub[90 + t]; c3.hi = v.x; c3.lo = v.y; }
        if (t < 81) { float2 v = sub[9 + t]; s2h[0][t] = v.x; s2l[0][t] = v.y; }
        if (t < 9)  { float2 v = sub[t];     s1h[0][t] = v.x; s1l[0][t] = v.y; }
        // batch-1 operands (folds 1..NB1)
        #pragma unroll
        for (int p = 1; p <= NB1; ++p) {
            const float2* B = sub + (long)p * SIGLEN;
            ob1[p - 1] = B[k];
            ob2[p - 1] = B[9 + j * 9 + k];
            ob3[p - 1] = B[90 + t];
        }
    }
    __syncthreads();

    int cur = 0;
    #pragma unroll
    for (int p = 1; p <= NB1; ++p) {
        if (act) {
            df2 b1k  = { ob1[p - 1].x, ob1[p - 1].y };
            df2 b2jk = { ob2[p - 1].x, ob2[p - 1].y };
            df2 b3   = { ob3[p - 1].x, ob3[p - 1].y };
            df2 a1i  = { s1h[cur][i],         s1l[cur][i] };
            df2 a2ij = { s2h[cur][i * 9 + j], s2l[cur][i * 9 + j] };
            c3 = df_add2(c3, b3);
            c3 = df_fmaf2(c3, a1i, b2jk);
            c3 = df_fmaf2(c3, a2ij, b1k);
            if (t < 81) {
                df2 a1s = { s1h[cur][t / 9], s1l[cur][t / 9] };
                df2 c2  = { s2h[cur][t],     s2l[cur][t] };
                c2 = df_add2(c2, b2jk);
                c2 = df_fmaf2(c2, a1s, b1k);
                s2h[cur ^ 1][t] = c2.hi;  s2l[cur ^ 1][t] = c2.lo;
            }
            if (t < 9) {
                df2 c1 = { s1h[cur][t], s1l[cur][t] };
                c1 = df_add2(c1, b1k);
                s1h[cur ^ 1][t] = c1.hi;  s1l[cur ^ 1][t] = c1.lo;
            }
        }
        __syncthreads();
        cur ^= 1;
    }

    // batch-2 operands (folds NB1+1 .. SUBT-1)
    float2 pb1[NB2], pb2[NB2], pb3[NB2];
    if (act) {
        #pragma unroll
        for (int q = 0; q < NB2; ++q) {
            const float2* B = sub + (long)(NB1 + 1 + q) * SIGLEN;
            pb1[q] = B[k];
            pb2[q] = B[9 + j * 9 + k];
            pb3[q] = B[90 + t];
        }
    }
    #pragma unroll
    for (int q = 0; q < NB2; ++q) {
        if (act) {
            df2 b1k  = { pb1[q].x, pb1[q].y };
            df2 b2jk = { pb2[q].x, pb2[q].y };
            df2 b3   = { pb3[q].x, pb3[q].y };
            df2 a1i  = { s1h[cur][i],         s1l[cur][i] };
            df2 a2ij = { s2h[cur][i * 9 + j], s2l[cur][i * 9 + j] };
            c3 = df_add2(c3, b3);
            c3 = df_fmaf2(c3, a1i, b2jk);
            c3 = df_fmaf2(c3, a2ij, b1k);
            if (t < 81) {
                df2 a1s = { s1h[cur][t / 9], s1l[cur][t / 9] };
                df2 c2  = { s2h[cur][t],     s2l[cur][t] };
                c2 = df_add2(c2, b2jk);
                c2 = df_fmaf2(c2, a1s, b1k);
                s2h[cur ^ 1][t] = c2.hi;  s2l[cur ^ 1][t] = c2.lo;
            }
            if (t < 9) {
                df2 c1 = { s1h[cur][t], s1l[cur][t] };
                c1 = df_add2(c1, b1k);
                s1h[cur ^ 1][t] = c1.hi;  s1l[cur ^ 1][t] = c1.lo;
            }
        }
        __syncthreads();
        cur ^= 1;
    }

    // ---- log3 (fp64, one shot) -> flat (fp32) ----
    if (act) {
        double s1i = (double)s1h[cur][i] + (double)s1l[cur][i];
        double s1j = (double)s1h[cur][j] + (double)s1l[cur][j];
        double s1k = (double)s1h[cur][k] + (double)s1l[cur][k];
        double s2jk = (double)s2h[cur][j * 9 + k] + (double)s2l[cur][j * 9 + k];
        double s2ij = (double)s2h[cur][i * 9 + j] + (double)s2l[cur][i * 9 + j];
        double c3d  = (double)c3.hi + (double)c3.lo;
        double l3 = c3d - 0.5 * (s1i * s2jk + s2ij * s1k) + s1i * s1j * s1k * (1.0 / 3.0);
        flat_sh[90 + t] = (float)l3;
        if (t < 81) {
            double a = (double)s2h[cur][t] + (double)s2l[cur][t];
            double u = (double)s1h[cur][t / 9] + (double)s1l[cur][t / 9];
            double w = (double)s1h[cur][t % 9] + (double)s1l[cur][t % 9];
            flat_sh[9 + t] = (float)(a - 0.5 * u * w);
        }
        if (t < 9) flat_sh[t] = __fadd_rn(s1h[cur][t], s1l[cur][t]);
    }
    __syncthreads();

    // ---- MLP layer 1: h = relu(flat @ W1 + b1) ----
    if (t < 512) {
        const int slice = t >> 6;   // 0..7
        const int jg    = t & 63;   // 0..63
        float4 acc = make_float4(0.f, 0.f, 0.f, 0.f);
        #pragma unroll 4
        for (int m = slice; m < SIGLEN; m += 8) {
            float fm = flat_sh[m];
            float4 w = *reinterpret_cast<const float4*>(W1 + (long)m * HID + jg * 4);
            acc.x = fmaf(fm, w.x, acc.x);
            acc.y = fmaf(fm, w.y, acc.y);
            acc.z = fmaf(fm, w.z, acc.z);
            acc.w = fmaf(fm, w.w, acc.w);
        }
        *reinterpret_cast<float4*>(&hred[slice][jg * 4]) = acc;
    }
    __syncthreads();

    // ---- MLP layer 2 ----
    if (t < HID) {
        float h = b1v[t];
        #pragma unroll
        for (int s = 0; s < 8; ++s) h += hred[s][t];
        h = fmaxf(h, 0.0f);
        float p = h * W2[t];
        #pragma unroll
        for (int off = 16; off > 0; off >>= 1)
            p += __shfl_down_sync(0xffffffff, p, off);
        if ((t & 31) == 0) osum[t >> 5] = p;
    }
    __syncthreads();
    if (t == 0) {
        float s = b2v[0];
        #pragma unroll
        for (int w = 0; w < 8; ++w) s += osum[w];
        out[b] = s;
    }
}

// =====================================================================
extern "C" void kernel_launch(void* const* d_in, const int* in_sizes, int n_in,
                              void* d_out, int out_size)
{
    const float* x  = (const float*)d_in[0];
    const float* W1 = (const float*)d_in[1];
    const float* b1 = (const float*)d_in[2];
    const float* W2 = (const float*)d_in[3];
    const float* b2 = (const float*)d_in[4];

    sig_partial_kernel<<<dim3(GRANGES, BATCH), 96>>>(x);
    combine_kernel<<<dim3(SUBT, BATCH), 768>>>();
    final_kernel<<<BATCH, 768>>>(W1, b1, W2, b2, (float*)d_out);
}